// round 1
// baseline (speedup 1.0000x reference)
#include <cuda_runtime.h>
#include <cstdint>

// FeedForwardQuantum fused kernel.
//   q = cos(x[:, :NQ] + theta)                  (precompute kernel -> g_q)
//   out = relu(q @ W1^T + b1) @ W2^T + b2       (fused: A-tile of GEMM2 computed on the fly)
//
// GEMM2: M=16384, N=E=1024, K=FFN=4096. tf32 mma.sync with fp32 accumulate.

#define NQ      10
#define BM      128
#define BN      128
#define BK      32
#define THREADS 256
#define APAD    (BK + 4)   // smem row stride 36 floats: bank(g,tg) = 4g+tg -> conflict-free

// Scratch for q = cos(x[:, :NQ] + theta). Max 32768 tokens.
__device__ float g_q[32768 * NQ];

__global__ void qcos_kernel(const float* __restrict__ x,
                            const float* __restrict__ theta,
                            int M, int E) {
    int t = blockIdx.x * blockDim.x + threadIdx.x;
    if (t >= M) return;
    const float* xr = x + (size_t)t * E;
    float th[NQ];
#pragma unroll
    for (int i = 0; i < NQ; i++) th[i] = __ldg(theta + i);
#pragma unroll
    for (int i = 0; i < NQ; i++) g_q[t * NQ + i] = cosf(xr[i] + th[i]);
}

__device__ __forceinline__ uint32_t f2tf32(float f) {
    uint32_t r;
    asm("cvt.rna.tf32.f32 %0, %1;" : "=r"(r) : "f"(f));
    return r;
}

#define MMA_TF32(d, a, b)                                               \
    asm volatile(                                                       \
        "mma.sync.aligned.m16n8k8.row.col.f32.tf32.tf32.f32 "           \
        "{%0,%1,%2,%3}, {%4,%5,%6,%7}, {%8,%9}, {%0,%1,%2,%3};"         \
        : "+f"((d)[0]), "+f"((d)[1]), "+f"((d)[2]), "+f"((d)[3])        \
        : "r"((a)[0]), "r"((a)[1]), "r"((a)[2]), "r"((a)[3]),           \
          "r"((b)[0]), "r"((b)[1]))

__global__ void __launch_bounds__(THREADS, 2)
ffn_kernel(const float* __restrict__ W1,
           const float* __restrict__ b1,
           const float* __restrict__ W2,
           const float* __restrict__ b2,
           float* __restrict__ out,
           int M, int K, int E) {
    __shared__ float As[BM][APAD];   // h tile (tf32-rounded), row-major [m][k]
    __shared__ float Bs[BN][APAD];   // W2 tile (tf32-rounded), [n][k]
    __shared__ float qs[BM][NQ];     // q slab for this token tile

    const int tid  = threadIdx.x;
    const int lane = tid & 31;
    const int warp = tid >> 5;
    const int wm   = (warp & 3) * 32;   // warp M offset within CTA tile
    const int wn   = (warp >> 2) * 64;  // warp N offset
    const int g    = lane >> 2;         // groupID
    const int tg   = lane & 3;          // thread-in-group

    const int mblk = blockIdx.y * BM;   // token base
    const int nblk = blockIdx.x * BN;   // output-feature base

    // Load q slab (coalesced; consumed after the first __syncthreads in the loop).
    {
        float* qsf = &qs[0][0];
        const float* qg = g_q + (size_t)mblk * NQ;
        for (int i = tid; i < BM * NQ; i += THREADS) qsf[i] = qg[i];
    }

    float acc[2][8][4];
#pragma unroll
    for (int mi = 0; mi < 2; mi++)
#pragma unroll
        for (int ni = 0; ni < 8; ni++)
#pragma unroll
            for (int j = 0; j < 4; j++) acc[mi][ni][j] = 0.f;

    // Register prefetch buffers (double-buffer vs. SMEM phases).
    float4 w2r[4];
    float2 w1r[5];
    float  b1r;
    const int kcol  = tid & 31;         // this thread's K-column inside the chunk
    const int mbase = (tid >> 5) * 16;  // this thread's 16-row M slab for A compute

    // ---- prefetch chunk 0 ----
    {
#pragma unroll
        for (int p = 0; p < 4; p++) {
            int v  = p * THREADS + tid;
            int n  = v >> 3;
            int k4 = (v & 7) << 2;
            w2r[p] = *(const float4*)(W2 + (size_t)(nblk + n) * K + k4);
        }
        const float* wrow = W1 + (size_t)kcol * NQ;
#pragma unroll
        for (int j = 0; j < 5; j++) w1r[j] = *(const float2*)(wrow + 2 * j);
        b1r = b1[kcol];
    }

    for (int kc = 0; kc < K; kc += BK) {
        __syncthreads();   // previous mma phase done; smem free (also fences qs on iter 0)

        // ---- STS B (tf32-rounded), float4 stores ----
#pragma unroll
        for (int p = 0; p < 4; p++) {
            int v  = p * THREADS + tid;
            int n  = v >> 3;
            int k4 = (v & 7) << 2;
            float4 t4;
            t4.x = __uint_as_float(f2tf32(w2r[p].x));
            t4.y = __uint_as_float(f2tf32(w2r[p].y));
            t4.z = __uint_as_float(f2tf32(w2r[p].z));
            t4.w = __uint_as_float(f2tf32(w2r[p].w));
            *(float4*)&Bs[n][k4] = t4;
        }

        // ---- compute A tile: h[m, kc+kcol] = relu(q[m,:] . W1[kc+kcol,:] + b1) ----
#pragma unroll
        for (int mm = 0; mm < 16; mm++) {
            int m = mbase + mm;
            float s = b1r;
            s += qs[m][0] * w1r[0].x; s += qs[m][1] * w1r[0].y;
            s += qs[m][2] * w1r[1].x; s += qs[m][3] * w1r[1].y;
            s += qs[m][4] * w1r[2].x; s += qs[m][5] * w1r[2].y;
            s += qs[m][6] * w1r[3].x; s += qs[m][7] * w1r[3].y;
            s += qs[m][8] * w1r[4].x; s += qs[m][9] * w1r[4].y;
            As[m][kcol] = __uint_as_float(f2tf32(fmaxf(s, 0.f)));
        }

        __syncthreads();

        // ---- prefetch next chunk (latency hidden under the mma phase) ----
        int kn = kc + BK;
        if (kn < K) {
#pragma unroll
            for (int p = 0; p < 4; p++) {
                int v  = p * THREADS + tid;
                int n  = v >> 3;
                int k4 = (v & 7) << 2;
                w2r[p] = *(const float4*)(W2 + (size_t)(nblk + n) * K + kn + k4);
            }
            const float* wrow = W1 + (size_t)(kn + kcol) * NQ;
#pragma unroll
            for (int j = 0; j < 5; j++) w1r[j] = *(const float2*)(wrow + 2 * j);
            b1r = b1[kn + kcol];
        }

        // ---- mma phase: 4 k-steps of 8 ----
#pragma unroll
        for (int kk = 0; kk < 4; kk++) {
            const int k0 = kk * 8;
            uint32_t a[2][4];
#pragma unroll
            for (int mi = 0; mi < 2; mi++) {
                int r = wm + mi * 16 + g;
                a[mi][0] = __float_as_uint(As[r    ][k0 + tg    ]);
                a[mi][1] = __float_as_uint(As[r + 8][k0 + tg    ]);
                a[mi][2] = __float_as_uint(As[r    ][k0 + tg + 4]);
                a[mi][3] = __float_as_uint(As[r + 8][k0 + tg + 4]);
            }
#pragma unroll
            for (int ni = 0; ni < 8; ni++) {
                int n = wn + ni * 8 + g;
                uint32_t b[2];
                b[0] = __float_as_uint(Bs[n][k0 + tg    ]);
                b[1] = __float_as_uint(Bs[n][k0 + tg + 4]);
                MMA_TF32(acc[0][ni], a[0], b);
                MMA_TF32(acc[1][ni], a[1], b);
            }
        }
    }

    // ---- epilogue: out = acc + b2, float2 stores ----
#pragma unroll
    for (int mi = 0; mi < 2; mi++) {
        int m0 = mblk + wm + mi * 16 + g;
#pragma unroll
        for (int ni = 0; ni < 8; ni++) {
            int n = nblk + wn + ni * 8 + 2 * tg;
            float2 bv = *(const float2*)(b2 + n);
            float2 o0, o1;
            o0.x = acc[mi][ni][0] + bv.x;  o0.y = acc[mi][ni][1] + bv.y;
            o1.x = acc[mi][ni][2] + bv.x;  o1.y = acc[mi][ni][3] + bv.y;
            *(float2*)(out + (size_t)m0 * E + n)       = o0;
            *(float2*)(out + (size_t)(m0 + 8) * E + n) = o1;
        }
    }
}

extern "C" void kernel_launch(void* const* d_in, const int* in_sizes, int n_in,
                              void* d_out, int out_size) {
    const float* x     = (const float*)d_in[0];
    const float* theta = (const float*)d_in[1];
    const float* W1    = (const float*)d_in[2];
    const float* b1    = (const float*)d_in[3];
    const float* W2    = (const float*)d_in[4];
    const float* b2    = (const float*)d_in[5];
    float* out = (float*)d_out;

    const int E   = in_sizes[5];        // 1024 (b2)
    const int FFN = in_sizes[3];        // 4096 (b1)
    const int M   = in_sizes[0] / E;    // 16384 tokens

    qcos_kernel<<<(M + 255) / 256, 256>>>(x, theta, M, E);

    dim3 grid(E / BN, M / BM);          // (8, 128)
    ffn_kernel<<<grid, THREADS>>>(W1, b1, W2, b2, out, M, FFN, E);
}